// round 1
// baseline (speedup 1.0000x reference)
#include <cuda_runtime.h>

#define N_NODES 32768
#define N_EDGES 524288
#define F 128
#define NRBF 32
#define EVD 16
#define NDEG 4
#define NFEAT 36
#define RSQRT_D 0.17677669529663687f
#define NPB 16
#define TILE_E 8
#define NTILES (N_EDGES / TILE_E)

// node-phase scratch (device globals: allocation-free)
__device__ float g_q_inv[N_NODES * F];
__device__ float g_k_inv[N_NODES * F];
__device__ float g_v_inv[N_NODES * F];
__device__ float g_q_ev[N_NODES * F];
__device__ float g_k_ev[N_NODES * F];

__device__ __forceinline__ float silu(float x) { return x / (1.0f + __expf(-x)); }

__device__ __forceinline__ void red4(float* addr, float a, float b, float c, float d) {
    asm volatile("red.global.add.v4.f32 [%0], {%1,%2,%3,%4};"
                 :: "l"(addr), "f"(a), "f"(b), "f"(c), "f"(d) : "memory");
}

// ---------------------------------------------------------------------------
// Node kernel: q_inv/k_inv/v_inv/q_ev/k_ev = per-head [32x32] projections.
// Block = 128 threads (thread t owns output feature f=t: h=t/32, e=t%32).
// All 5 weight tensors (80KB) staged in dynamic shared; 16 nodes per block,
// 4-node register blocking to amortize weight LDS.
// ---------------------------------------------------------------------------
__global__ void node_kernel(const float* __restrict__ x,
                            const float* __restrict__ Wq, const float* __restrict__ Wk,
                            const float* __restrict__ Wv, const float* __restrict__ Wqe,
                            const float* __restrict__ Wke) {
    extern __shared__ float sm[];
    float* w_s = sm;                 // 5 * 4096
    float* x_s = sm + 5 * 4096;      // NPB * 128
    int t = threadIdx.x;

    for (int i = t; i < 4096; i += 128) {
        w_s[i]            = Wq[i];
        w_s[4096 + i]     = Wk[i];
        w_s[2 * 4096 + i] = Wv[i];
        w_s[3 * 4096 + i] = Wqe[i];
        w_s[4 * 4096 + i] = Wke[i];
    }
    int base = blockIdx.x * NPB;
    for (int i = t; i < NPB * F; i += 128) x_s[i] = x[(size_t)base * F + i];
    __syncthreads();

    int h = t >> 5, e = t & 31;
    const float* wq  = w_s + h * 1024 + e;      // stride 32 over d
    const float* wk  = wq + 4096;
    const float* wv  = wq + 2 * 4096;
    const float* wqe = wq + 3 * 4096;
    const float* wke = wq + 4 * 4096;

    for (int n0 = 0; n0 < NPB; n0 += 4) {
        float aq[4]  = {0, 0, 0, 0}, ak[4]  = {0, 0, 0, 0}, av[4] = {0, 0, 0, 0};
        float aqe[4] = {0, 0, 0, 0}, ake[4] = {0, 0, 0, 0};
#pragma unroll 8
        for (int d = 0; d < 32; d++) {
            float q  = wq[d * 32];
            float k  = wk[d * 32];
            float v  = wv[d * 32];
            float qe = wqe[d * 32];
            float ke = wke[d * 32];
#pragma unroll
            for (int n = 0; n < 4; n++) {
                float xv = x_s[(n0 + n) * F + h * 32 + d];  // warp-broadcast
                aq[n]  = fmaf(xv, q,  aq[n]);
                ak[n]  = fmaf(xv, k,  ak[n]);
                av[n]  = fmaf(xv, v,  av[n]);
                aqe[n] = fmaf(xv, qe, aqe[n]);
                ake[n] = fmaf(xv, ke, ake[n]);
            }
        }
#pragma unroll
        for (int n = 0; n < 4; n++) {
            size_t node = base + n0 + n;
            g_q_inv[node * F + t] = silu(aq[n]);
            g_k_inv[node * F + t] = silu(ak[n]);
            g_v_inv[node * F + t] = av[n];
            g_q_ev[node * F + t]  = silu(aqe[n]);
            g_k_ev[node * F + t]  = silu(ake[n]);
        }
    }
}

// ---------------------------------------------------------------------------
// Edge kernel: 256 threads = 8 warps, tile of 8 edges per iteration.
// Thread t owns output column f of Wf_inv (t<128) or Wf_ev (t>=128),
// column weights cached in 36 registers. Warps 0-3: inv heads 0-3,
// warps 4-7: ev heads 0-3. Scatter via red.global.add.v4.f32.
// ---------------------------------------------------------------------------
__global__ void edge_kernel(const float* __restrict__ ev,
                            const float* __restrict__ rbf,
                            const float* __restrict__ sh,
                            const float* __restrict__ cutoffs,
                            const float* __restrict__ Wf_inv, const float* __restrict__ bf_inv,
                            const float* __restrict__ Wf_ev,  const float* __restrict__ bf_ev,
                            const int* __restrict__ senders,
                            const int* __restrict__ receivers,
                            float* __restrict__ out_inv,   // [N,128]
                            float* __restrict__ out_ev)    // [N,16]
{
    __shared__ float feat_s[TILE_E][40];   // 36 used, pad for float4 align
    __shared__ float sq_s[TILE_E][16];
    __shared__ int   s_s[TILE_E], r_s[TILE_E];
    __shared__ float c_s[TILE_E];
    __shared__ float aev_s[TILE_E][4];
    __shared__ float mev_s[TILE_E][16];

    int t = threadIdx.x;
    int w = t >> 5, l = t & 31;
    bool is_inv = (w < 4);
    int h = w & 3;
    int f = t & 127;

    float wcol[NFEAT];
    const float* Wf = is_inv ? Wf_inv : Wf_ev;
#pragma unroll
    for (int j = 0; j < NFEAT; j++) wcol[j] = Wf[j * F + f];
    float bias = (is_inv ? bf_inv : bf_ev)[f];

    for (int tile = blockIdx.x; tile < NTILES; tile += gridDim.x) {
        int e0 = tile * TILE_E;

        // A1: ev differences + per-edge scalars
        if (t < TILE_E * 16) {
            int e = t >> 4, j = t & 15;
            int ss = senders[e0 + e], rr = receivers[e0 + e];
            float d = ev[(size_t)ss * EVD + j] - ev[(size_t)rr * EVD + j];
            sq_s[e][j] = d * d;
            if (j == 0) { s_s[e] = ss; r_s[e] = rr; c_s[e] = cutoffs[e0 + e]; }
        }
        // A2: rbf -> feat[0:32]
        feat_s[t >> 5][t & 31] = rbf[(size_t)e0 * NRBF + t];
        __syncthreads();
        // A3: per-degree invariants -> feat[32:36]
        if (t < TILE_E * NDEG) {
            int e = t >> 2, dg = t & 3;
            int off = (dg == 0) ? 0 : (dg == 1) ? 1 : (dg == 2) ? 4 : 9;
            int cnt = 2 * dg + 1;
            float s = 0.f;
            for (int i = 0; i < cnt; i++) s += sq_s[e][off + i];
            feat_s[e][NRBF + dg] = s;
        }
        __syncthreads();

        // B: per-edge fw column + attention + inv scatter
        for (int e = 0; e < TILE_E; e++) {
            float acc0 = bias, acc1 = 0.f;
            const float4* fv4 = (const float4*)(&feat_s[e][0]);
#pragma unroll
            for (int jq = 0; jq < 9; jq++) {
                float4 fv = fv4[jq];
                acc0 = fmaf(fv.x, wcol[4 * jq + 0], acc0);
                acc1 = fmaf(fv.y, wcol[4 * jq + 1], acc1);
                acc0 = fmaf(fv.z, wcol[4 * jq + 2], acc0);
                acc1 = fmaf(fv.w, wcol[4 * jq + 3], acc1);
            }
            float fw = acc0 + acc1;
            int ss = s_s[e], rr = r_s[e];
            float cut = c_s[e];
            if (is_inv) {
                float q = g_q_inv[(size_t)rr * F + h * 32 + l];
                float k = g_k_inv[(size_t)ss * F + h * 32 + l];
                float v = g_v_inv[(size_t)ss * F + h * 32 + l];
                float p = q * k * fw;
#pragma unroll
                for (int o = 16; o > 0; o >>= 1) p += __shfl_xor_sync(0xffffffffu, p, o);
                float m = p * RSQRT_D * cut * v;
                int src = (l & 7) * 4;
                float m0 = __shfl_sync(0xffffffffu, m, src + 0);
                float m1 = __shfl_sync(0xffffffffu, m, src + 1);
                float m2 = __shfl_sync(0xffffffffu, m, src + 2);
                float m3 = __shfl_sync(0xffffffffu, m, src + 3);
                if (l < 8) red4(out_inv + (size_t)rr * F + h * 32 + l * 4, m0, m1, m2, m3);
            } else {
                float q = g_q_ev[(size_t)rr * F + h * 32 + l];
                float k = g_k_ev[(size_t)ss * F + h * 32 + l];
                float p = q * k * fw;
#pragma unroll
                for (int o = 16; o > 0; o >>= 1) p += __shfl_xor_sync(0xffffffffu, p, o);
                if (l == 0) aev_s[e][h] = p * RSQRT_D;
            }
        }
        __syncthreads();

        // C1: ev messages (repeat a_ev per degree block)
        if (t < TILE_E * 16) {
            int e = t >> 4, j = t & 15;
            int dg = (j == 0) ? 0 : (j < 4) ? 1 : (j < 9) ? 2 : 3;
            mev_s[e][j] = c_s[e] * aev_s[e][dg] * sh[(size_t)(e0 + e) * EVD + j];
        }
        __syncthreads();
        // C2: ev scatter (v4 atomics)
        if (t < TILE_E * 4) {
            int e = t >> 2, qd = t & 3;
            float4 mv = *(const float4*)(&mev_s[e][qd * 4]);
            red4(out_ev + (size_t)r_s[e] * EVD + qd * 4, mv.x, mv.y, mv.z, mv.w);
        }
        __syncthreads();
    }
}

// ---------------------------------------------------------------------------
extern "C" void kernel_launch(void* const* d_in, const int* in_sizes, int n_in,
                              void* d_out, int out_size) {
    const float* inv_features = (const float*)d_in[0];
    const float* ev_features  = (const float*)d_in[1];
    const float* rbf          = (const float*)d_in[2];
    const float* sh           = (const float*)d_in[3];
    const float* cutoffs      = (const float*)d_in[4];
    const float* W_q_inv      = (const float*)d_in[5];
    const float* W_k_inv      = (const float*)d_in[6];
    const float* W_v_inv      = (const float*)d_in[7];
    const float* W_q_ev       = (const float*)d_in[8];
    const float* W_k_ev       = (const float*)d_in[9];
    const float* Wf_inv       = (const float*)d_in[10];
    const float* bf_inv       = (const float*)d_in[11];
    const float* Wf_ev        = (const float*)d_in[12];
    const float* bf_ev        = (const float*)d_in[13];
    const int*   senders      = (const int*)d_in[14];
    const int*   receivers    = (const int*)d_in[15];

    float* out     = (float*)d_out;
    float* out_inv = out;                               // [N,128]
    float* out_ev  = out + (size_t)N_NODES * F;         // [N,16]

    cudaMemsetAsync(d_out, 0, (size_t)out_size * sizeof(float));

    size_t smem = (5 * 4096 + NPB * F) * sizeof(float); // 88 KB
    cudaFuncSetAttribute(node_kernel, cudaFuncAttributeMaxDynamicSharedMemorySize, (int)smem);
    node_kernel<<<N_NODES / NPB, 128, smem>>>(inv_features, W_q_inv, W_k_inv, W_v_inv,
                                              W_q_ev, W_k_ev);
    edge_kernel<<<2048, 256>>>(ev_features, rbf, sh, cutoffs,
                               Wf_inv, bf_inv, Wf_ev, bf_ev,
                               senders, receivers, out_inv, out_ev);
}

// round 2
// speedup vs baseline: 1.3879x; 1.3879x over previous
#include <cuda_runtime.h>

#define N_NODES 32768
#define N_EDGES 524288
#define F 128
#define NRBF 32
#define EVD 16
#define NDEG 4
#define NFEAT 36
#define RSQRT_D 0.17677669529663687f
#define NPB 16
#define TILE_E 16
#define NTILES (N_EDGES / TILE_E)

// node-phase scratch (device globals: allocation-free)
__device__ float g_q_inv[N_NODES * F];
__device__ float g_k_inv[N_NODES * F];
__device__ float g_v_inv[N_NODES * F];
__device__ float g_q_ev[N_NODES * F];
__device__ float g_k_ev[N_NODES * F];

union F2 { float2 f; unsigned long long u; };

__device__ __forceinline__ float silu(float x) { return x / (1.0f + __expf(-x)); }

__device__ __forceinline__ unsigned long long fma2(unsigned long long a,
                                                   unsigned long long b,
                                                   unsigned long long c) {
    unsigned long long d;
    asm("fma.rn.f32x2 %0, %1, %2, %3;" : "=l"(d) : "l"(a), "l"(b), "l"(c));
    return d;
}

__device__ __forceinline__ void red4(float* addr, float a, float b, float c, float d) {
    asm volatile("red.global.add.v4.f32 [%0], {%1,%2,%3,%4};"
                 :: "l"(addr), "f"(a), "f"(b), "f"(c), "f"(d) : "memory");
}

__device__ __forceinline__ void red1(float* addr, float a) {
    asm volatile("red.global.add.f32 [%0], %1;" :: "l"(addr), "f"(a) : "memory");
}

// ---------------------------------------------------------------------------
// Node kernel: q_inv/k_inv/v_inv/q_ev/k_ev = per-head [32x32] projections.
// ---------------------------------------------------------------------------
__global__ void node_kernel(const float* __restrict__ x,
                            const float* __restrict__ Wq, const float* __restrict__ Wk,
                            const float* __restrict__ Wv, const float* __restrict__ Wqe,
                            const float* __restrict__ Wke) {
    extern __shared__ float sm[];
    float* w_s = sm;                 // 5 * 4096
    float* x_s = sm + 5 * 4096;      // NPB * 128
    int t = threadIdx.x;

    for (int i = t; i < 4096; i += 128) {
        w_s[i]            = Wq[i];
        w_s[4096 + i]     = Wk[i];
        w_s[2 * 4096 + i] = Wv[i];
        w_s[3 * 4096 + i] = Wqe[i];
        w_s[4 * 4096 + i] = Wke[i];
    }
    int base = blockIdx.x * NPB;
    for (int i = t; i < NPB * F; i += 128) x_s[i] = x[(size_t)base * F + i];
    __syncthreads();

    int h = t >> 5, e = t & 31;
    const float* wq  = w_s + h * 1024 + e;      // stride 32 over d
    const float* wk  = wq + 4096;
    const float* wv  = wq + 2 * 4096;
    const float* wqe = wq + 3 * 4096;
    const float* wke = wq + 4 * 4096;

    for (int n0 = 0; n0 < NPB; n0 += 4) {
        float aq[4]  = {0, 0, 0, 0}, ak[4]  = {0, 0, 0, 0}, av[4] = {0, 0, 0, 0};
        float aqe[4] = {0, 0, 0, 0}, ake[4] = {0, 0, 0, 0};
#pragma unroll 8
        for (int d = 0; d < 32; d++) {
            float q  = wq[d * 32];
            float k  = wk[d * 32];
            float v  = wv[d * 32];
            float qe = wqe[d * 32];
            float ke = wke[d * 32];
#pragma unroll
            for (int n = 0; n < 4; n++) {
                float xv = x_s[(n0 + n) * F + h * 32 + d];  // warp-broadcast
                aq[n]  = fmaf(xv, q,  aq[n]);
                ak[n]  = fmaf(xv, k,  ak[n]);
                av[n]  = fmaf(xv, v,  av[n]);
                aqe[n] = fmaf(xv, qe, aqe[n]);
                ake[n] = fmaf(xv, ke, ake[n]);
            }
        }
#pragma unroll
        for (int n = 0; n < 4; n++) {
            size_t node = base + n0 + n;
            g_q_inv[node * F + t] = silu(aq[n]);
            g_k_inv[node * F + t] = silu(ak[n]);
            g_v_inv[node * F + t] = av[n];
            g_q_ev[node * F + t]  = silu(aqe[n]);
            g_k_ev[node * F + t]  = silu(ake[n]);
        }
    }
}

// ---------------------------------------------------------------------------
// Edge kernel: 256 threads = 8 warps, tile of 16 edges.
// Thread t owns output column f (t&127) of Wf_inv (warps 0-3) or Wf_ev
// (warps 4-7); column weights held as 18 packed f32x2 registers.
// Edges processed in register-blocked groups of 4 for ILP.
// ---------------------------------------------------------------------------
__global__ void __launch_bounds__(256, 3)
edge_kernel(const float* __restrict__ ev,
            const float* __restrict__ rbf,
            const float* __restrict__ sh,
            const float* __restrict__ cutoffs,
            const float* __restrict__ Wf_inv, const float* __restrict__ bf_inv,
            const float* __restrict__ Wf_ev,  const float* __restrict__ bf_ev,
            const int* __restrict__ senders,
            const int* __restrict__ receivers,
            float* __restrict__ out_inv,   // [N,128]
            float* __restrict__ out_ev)    // [N,16]
{
    __shared__ float feat_s[TILE_E][40];   // 36 used, pad keeps float4 align
    __shared__ float sq_s[TILE_E][16];
    __shared__ int   s_s[TILE_E], r_s[TILE_E];
    __shared__ float c_s[TILE_E];
    __shared__ float aev_s[TILE_E][4];

    int t = threadIdx.x;
    int w = t >> 5, l = t & 31;
    bool is_inv = (w < 4);
    int h = w & 3;
    int f = t & 127;

    const float* Wf = is_inv ? Wf_inv : Wf_ev;
    unsigned long long wcol2[18];
#pragma unroll
    for (int j = 0; j < 18; j++) {
        F2 tmp;
        tmp.f = make_float2(Wf[(2 * j) * F + f], Wf[(2 * j + 1) * F + f]);
        wcol2[j] = tmp.u;
    }
    float bias = (is_inv ? bf_inv : bf_ev)[f];
    const float* gq = is_inv ? g_q_inv : g_q_ev;
    const float* gk = is_inv ? g_k_inv : g_k_ev;

    for (int tile = blockIdx.x; tile < NTILES; tile += gridDim.x) {
        int e0 = tile * TILE_E;

        // A1: ev differences + per-edge scalars (all 256 threads)
        {
            int e = t >> 4, j = t & 15;
            int ss = senders[e0 + e], rr = receivers[e0 + e];
            float d = ev[(size_t)ss * EVD + j] - ev[(size_t)rr * EVD + j];
            sq_s[e][j] = d * d;
            if (j == 0) { s_s[e] = ss; r_s[e] = rr; c_s[e] = cutoffs[e0 + e]; }
        }
        // A2: rbf -> feat[0:32]  (512 floats, 2 per thread)
#pragma unroll
        for (int i = 0; i < 2; i++) {
            int idx = t + i * 256;
            feat_s[idx >> 5][idx & 31] = rbf[(size_t)e0 * NRBF + idx];
        }
        __syncthreads();
        // A3: per-degree invariants -> feat[32:36]
        if (t < TILE_E * NDEG) {
            int e = t >> 2, dg = t & 3;
            const int off = (dg == 0) ? 0 : (dg == 1) ? 1 : (dg == 2) ? 4 : 9;
            float s = 0.f;
            for (int i = 0; i <= 2 * dg; i++) s += sq_s[e][off + i];
            feat_s[e][NRBF + dg] = s;
        }
        __syncthreads();

        // B: fw column (packed f32x2) + attention + inv scatter, 4 edges/group
        for (int g = 0; g < TILE_E; g += 4) {
            float qv[4], kv[4], cut[4];
            int rr[4], ss[4];
#pragma unroll
            for (int u = 0; u < 4; u++) {
                int e = g + u;
                ss[u] = s_s[e]; rr[u] = r_s[e]; cut[u] = c_s[e];
                qv[u] = gq[(size_t)rr[u] * F + h * 32 + l];
                kv[u] = gk[(size_t)ss[u] * F + h * 32 + l];
            }
            float4 v4[4];
            if (is_inv && l < 8) {
#pragma unroll
                for (int u = 0; u < 4; u++)
                    v4[u] = *(const float4*)(g_v_inv + (size_t)ss[u] * F + h * 32 + l * 4);
            }
            float p[4];
#pragma unroll
            for (int u = 0; u < 4; u++) {
                const float4* fv4 = (const float4*)(&feat_s[g + u][0]);
                F2 a0, a1;
                a0.f = make_float2(bias, 0.f);
                a1.f = make_float2(0.f, 0.f);
#pragma unroll
                for (int jq = 0; jq < 9; jq++) {
                    float4 fv = fv4[jq];
                    F2 lo, hi;
                    lo.f = make_float2(fv.x, fv.y);
                    hi.f = make_float2(fv.z, fv.w);
                    a0.u = fma2(lo.u, wcol2[2 * jq], a0.u);
                    a1.u = fma2(hi.u, wcol2[2 * jq + 1], a1.u);
                }
                float fw = (a0.f.x + a1.f.x) + (a0.f.y + a1.f.y);
                p[u] = qv[u] * kv[u] * fw;
            }
#pragma unroll
            for (int o = 16; o > 0; o >>= 1) {
#pragma unroll
                for (int u = 0; u < 4; u++)
                    p[u] += __shfl_xor_sync(0xffffffffu, p[u], o);
            }
            if (is_inv) {
                if (l < 8) {
#pragma unroll
                    for (int u = 0; u < 4; u++) {
                        float ms = p[u] * RSQRT_D * cut[u];
                        red4(out_inv + (size_t)rr[u] * F + h * 32 + l * 4,
                             ms * v4[u].x, ms * v4[u].y, ms * v4[u].z, ms * v4[u].w);
                    }
                }
            } else {
                if (l == 0) {
#pragma unroll
                    for (int u = 0; u < 4; u++)
                        aev_s[g + u][h] = p[u] * RSQRT_D;
                }
            }
        }
        __syncthreads();

        // C: ev messages (repeat a_ev per degree block) + scalar red
        {
            int e = t >> 4, j = t & 15;
            int dg = (j == 0) ? 0 : (j < 4) ? 1 : (j < 9) ? 2 : 3;
            float m = c_s[e] * aev_s[e][dg] * sh[(size_t)(e0 + e) * EVD + j];
            red1(out_ev + (size_t)r_s[e] * EVD + j, m);
        }
        __syncthreads();
    }
}

// ---------------------------------------------------------------------------
extern "C" void kernel_launch(void* const* d_in, const int* in_sizes, int n_in,
                              void* d_out, int out_size) {
    const float* inv_features = (const float*)d_in[0];
    const float* ev_features  = (const float*)d_in[1];
    const float* rbf          = (const float*)d_in[2];
    const float* sh           = (const float*)d_in[3];
    const float* cutoffs      = (const float*)d_in[4];
    const float* W_q_inv      = (const float*)d_in[5];
    const float* W_k_inv      = (const float*)d_in[6];
    const float* W_v_inv      = (const float*)d_in[7];
    const float* W_q_ev       = (const float*)d_in[8];
    const float* W_k_ev       = (const float*)d_in[9];
    const float* Wf_inv       = (const float*)d_in[10];
    const float* bf_inv       = (const float*)d_in[11];
    const float* Wf_ev        = (const float*)d_in[12];
    const float* bf_ev        = (const float*)d_in[13];
    const int*   senders      = (const int*)d_in[14];
    const int*   receivers    = (const int*)d_in[15];

    float* out     = (float*)d_out;
    float* out_inv = out;                               // [N,128]
    float* out_ev  = out + (size_t)N_NODES * F;         // [N,16]

    cudaMemsetAsync(d_out, 0, (size_t)out_size * sizeof(float));

    size_t smem = (5 * 4096 + NPB * F) * sizeof(float); // 88 KB
    cudaFuncSetAttribute(node_kernel, cudaFuncAttributeMaxDynamicSharedMemorySize, (int)smem);
    node_kernel<<<N_NODES / NPB, 128, smem>>>(inv_features, W_q_inv, W_k_inv, W_v_inv,
                                              W_q_ev, W_k_ev);
    edge_kernel<<<2048, 256>>>(ev_features, rbf, sh, cutoffs,
                               Wf_inv, bf_inv, Wf_ev, bf_ev,
                               senders, receivers, out_inv, out_ev);
}